// round 1
// baseline (speedup 1.0000x reference)
#include <cuda_runtime.h>
#include <cstdint>

// Problem constants (fixed shapes per metadata): x = (8,32,256,256) fp32, K=3
#define PLANES 256            // B*C = 8*32
#define H      256
#define W      256
#define HO     254
#define WO     254
#define N_ELEM (PLANES * H * W)     // 16,777,216
#define N4     (N_ELEM / 4)

#define TW 64                 // output tile width
#define TH 32                 // output tile height
#define IN_W (TW + 2)         // 66
#define IN_H (TH + 2)         // 34

__device__ int g_counts[256];

// ---------------------------------------------------------------------------
// Kernel 1: zero the global histogram (device globals persist across graph
// replays, so this must run every launch).
// ---------------------------------------------------------------------------
__global__ void zero_counts_kernel() {
    g_counts[threadIdx.x] = 0;
}

// ---------------------------------------------------------------------------
// Kernel 2: 256-bin histogram of the whole tensor.
// 32 lane-interleaved shared sub-histograms: address = bin*32 + lane, so all
// 32 lanes of a warp always hit distinct banks -> conflict-free ATOMS.
// ---------------------------------------------------------------------------
__global__ void hist_kernel(const float4* __restrict__ x) {
    __shared__ int s_h[256 * 32];   // 32 KB
    for (int i = threadIdx.x; i < 256 * 32; i += blockDim.x) s_h[i] = 0;
    __syncthreads();

    const int lane = threadIdx.x & 31;
    const int stride = gridDim.x * blockDim.x;
    for (int i = blockIdx.x * blockDim.x + threadIdx.x; i < N4; i += stride) {
        float4 v = x[i];
        atomicAdd(&s_h[(((int)v.x) & 255) * 32 + lane], 1);
        atomicAdd(&s_h[(((int)v.y) & 255) * 32 + lane], 1);
        atomicAdd(&s_h[(((int)v.z) & 255) * 32 + lane], 1);
        atomicAdd(&s_h[(((int)v.w) & 255) * 32 + lane], 1);
    }
    __syncthreads();

    // Reduce 32 copies per bin; stagger start index so the column reads
    // (stride-32 addresses) are bank-conflict-free across the warp.
    const int t = threadIdx.x;   // blockDim.x == 256 -> one bin per thread
    int sum = 0;
    #pragma unroll
    for (int j = 0; j < 32; j++) {
        int i = (j + lane) & 31;
        sum += s_h[t * 32 + i];
    }
    atomicAdd(&g_counts[t], sum);
}

// ---------------------------------------------------------------------------
// Kernel 3: entropy pool. Per block: 64x32 output tile of one plane.
// Shared tile holds packed (count<<8 | value). Count clamped to 0xFFFFFF:
// safe because sum(counts) = 2^24, so at most one count can reach 2^24 and
// no other count can tie the clamped value.
// Tie-break: strict '<' scan in di-outer/dj-inner order == jnp.argmin first-min.
// ---------------------------------------------------------------------------
__global__ void pool_kernel(const float* __restrict__ x, float* __restrict__ out) {
    __shared__ int s_cnt[256];
    __shared__ unsigned int s_p[IN_H * IN_W];

    const int tid = threadIdx.x;
    s_cnt[tid] = g_counts[tid];            // blockDim.x == 256
    __syncthreads();

    const int plane = blockIdx.z;
    const int ty0 = blockIdx.y * TH;
    const int tx0 = blockIdx.x * TW;
    const float* xp = x + (size_t)plane * (H * W);

    for (int i = tid; i < IN_H * IN_W; i += 256) {
        int r = i / IN_W, c = i - r * IN_W;
        int gr = ty0 + r, gc = tx0 + c;
        unsigned int p = 0xFFFFFFFFu;
        if (gr < H && gc < W) {
            int v = ((int)xp[gr * W + gc]) & 255;
            unsigned int cnt = (unsigned int)s_cnt[v];
            if (cnt > 0xFFFFFFu) cnt = 0xFFFFFFu;
            p = (cnt << 8) | (unsigned int)v;
        }
        s_p[i] = p;
    }
    __syncthreads();

    const int tx  = tid & (TW - 1);        // 0..63
    const int tyb = tid >> 6;              // 0..3
    const int ocol = tx0 + tx;
    if (ocol >= WO) return;

    float* op = out + (size_t)plane * (HO * WO);
    #pragma unroll
    for (int rr = 0; rr < TH / 4; rr++) {
        const int ry = tyb * (TH / 4) + rr;     // 0..31
        const int orow = ty0 + ry;
        if (orow >= HO) break;
        const unsigned int* row0 = &s_p[ry * IN_W + tx];
        unsigned int bestc = 0xFFFFFFFFu;
        unsigned int bestp = 0;
        #pragma unroll
        for (int di = 0; di < 3; di++) {
            #pragma unroll
            for (int dj = 0; dj < 3; dj++) {
                unsigned int p = row0[di * IN_W + dj];
                unsigned int c = p >> 8;
                if (c < bestc) { bestc = c; bestp = p; }
            }
        }
        op[orow * WO + ocol] = (float)(bestp & 0xFFu);
    }
}

// ---------------------------------------------------------------------------
extern "C" void kernel_launch(void* const* d_in, const int* in_sizes, int n_in,
                              void* d_out, int out_size) {
    const float* x = (const float*)d_in[0];
    float* out = (float*)d_out;

    zero_counts_kernel<<<1, 256>>>();
    hist_kernel<<<1024, 256>>>((const float4*)x);

    dim3 grid((WO + TW - 1) / TW, (HO + TH - 1) / TH, PLANES);  // (4, 8, 256)
    pool_kernel<<<grid, 256>>>(x, out);
}